// round 16
// baseline (speedup 1.0000x reference)
#include <cuda_runtime.h>

// Problem constants
#define B_    16
#define CIN   512
#define N_    1024
#define HEADS_ 4
#define DH_   32
#define DV_   128
#define OTOT  768     // 128 (q) + 128 (k) + 512 (v) output channels

typedef unsigned long long ull;

// ---------------- f32x2 packed helpers (sm_103a FFMA2 path) ----------------
__device__ __forceinline__ ull f2pk(float lo, float hi) {
    ull r; asm("mov.b64 %0, {%1, %2};" : "=l"(r) : "f"(lo), "f"(hi)); return r;
}
__device__ __forceinline__ ull f2dup(float x) {
    ull r; asm("mov.b64 %0, {%1, %1};" : "=l"(r) : "f"(x)); return r;
}
__device__ __forceinline__ void f2upk(ull v, float& lo, float& hi) {
    asm("mov.b64 {%0, %1}, %2;" : "=f"(lo), "=f"(hi) : "l"(v));
}
__device__ __forceinline__ ull f2fma(ull a, ull b, ull c) {
    ull d; asm("fma.rn.f32x2 %0, %1, %2, %3;" : "=l"(d) : "l"(a), "l"(b), "l"(c)); return d;
}
__device__ __forceinline__ ull f2mul(ull a, ull b) {
    ull d; asm("mul.rn.f32x2 %0, %1, %2;" : "=l"(d) : "l"(a), "l"(b)); return d;
}
__device__ __forceinline__ ull lds64(const float* p) {
    float2 v = *reinterpret_cast<const float2*>(p);
    return f2pk(v.x, v.y);
}

// ---------------- scratch (device globals; no allocation allowed) ----------
__device__ float g_Weff[OTOT * CIN];       // folded conv+BN weights
__device__ float g_beff[OTOT];             // folded bias
__device__ float g_q[B_ * 128 * N_];       // [b][h*32+d][n]
__device__ float g_k[B_ * 128 * N_];       // [b][h*32+d][n]
__device__ float g_v[B_ * 512 * N_];       // [b][h*128+c][n]
__device__ float g_pos[HEADS_ * DH_ * N_]; // [h][d][n]

// ---------------- kernel 1: fold BN into conv weights ----------------------
__global__ void fold_kernel(
    const float* __restrict__ Wq, const float* __restrict__ bq,
    const float* __restrict__ qg, const float* __restrict__ qb,
    const float* __restrict__ qm, const float* __restrict__ qv,
    const float* __restrict__ Wk, const float* __restrict__ bk,
    const float* __restrict__ kg, const float* __restrict__ kb,
    const float* __restrict__ km, const float* __restrict__ kv,
    const float* __restrict__ Wv, const float* __restrict__ bv,
    const float* __restrict__ vg, const float* __restrict__ vb,
    const float* __restrict__ vm, const float* __restrict__ vv)
{
    int idx = blockIdx.x * blockDim.x + threadIdx.x;
    if (idx >= OTOT * CIN) return;
    int o = idx >> 9;
    int c = idx & 511;
    const float *W, *bb, *g, *be, *mu, *va;
    int ol;
    if (o < 128)      { W = Wq; bb = bq; g = qg; be = qb; mu = qm; va = qv; ol = o; }
    else if (o < 256) { W = Wk; bb = bk; g = kg; be = kb; mu = km; va = kv; ol = o - 128; }
    else              { W = Wv; bb = bv; g = vg; be = vb; mu = vm; va = vv; ol = o - 256; }
    float s = g[ol] * rsqrtf(va[ol] + 1e-5f);
    g_Weff[idx] = W[ol * CIN + c] * s;
    if (c == 0) g_beff[o] = (bb[ol] - mu[ol]) * s + be[ol];
}

// ---------------- kernel 2: pos = rel_h + rel_w, [h][d][n] -----------------
__global__ void pos_kernel(const float* __restrict__ rel_h,
                           const float* __restrict__ rel_w)
{
    int idx = blockIdx.x * blockDim.x + threadIdx.x;  // HEADS*DH*N = 131072
    if (idx >= HEADS_ * DH_ * N_) return;
    int n  = idx & (N_ - 1);
    int hd = idx >> 10;            // h*32 + d
    int w  = n >> 5;
    int hh = n & 31;
    g_pos[idx] = rel_h[hd * 32 + hh] + rel_w[hd * 32 + w];
}

// ---------------- kernel 3: fused QKV GEMM  Y[768,1024] = Weff @ x_b -------
// (R8 version — best measured.)  Rows 4*ty+i, col pairs 2*tx+32p.
__global__ __launch_bounds__(256) void qkv_gemm(const float* __restrict__ x)
{
    __shared__ float As[16][68];   // As[kk][m]  (A transposed in smem)
    __shared__ float Bs[16][68];   // Bs[kk][n]

    int b  = blockIdx.z;
    int m0 = blockIdx.y * 64;
    int n0 = blockIdx.x * 64;
    int tid = threadIdx.x;
    int ty = tid >> 4, tx = tid & 15;
    const float* xb = x + (size_t)b * CIN * N_;

    ull acc[4][2];
#pragma unroll
    for (int i = 0; i < 4; i++) { acc[i][0] = 0ull; acc[i][1] = 0ull; }

    for (int k0 = 0; k0 < CIN; k0 += 16) {
        {
            int row = tid >> 2;
            int cg  = (tid & 3) * 4;
            float4 av = *(const float4*)(g_Weff + (m0 + row) * CIN + k0 + cg);
            As[cg + 0][row] = av.x;
            As[cg + 1][row] = av.y;
            As[cg + 2][row] = av.z;
            As[cg + 3][row] = av.w;
        }
        {
            int nn = tid & 63;
            int kk = tid >> 6;
#pragma unroll
            for (int it = 0; it < 4; it++)
                Bs[kk + it * 4][nn] = xb[(size_t)(k0 + kk + it * 4) * N_ + n0 + nn];
        }
        __syncthreads();
#pragma unroll
        for (int kk = 0; kk < 16; kk++) {
            float4 a4 = *(const float4*)(&As[kk][4 * ty]);
            ull ad0 = f2dup(a4.x), ad1 = f2dup(a4.y), ad2 = f2dup(a4.z), ad3 = f2dup(a4.w);
            ull b0 = lds64(&Bs[kk][2 * tx]);
            ull b1 = lds64(&Bs[kk][2 * tx + 32]);
            acc[0][0] = f2fma(ad0, b0, acc[0][0]);
            acc[0][1] = f2fma(ad0, b1, acc[0][1]);
            acc[1][0] = f2fma(ad1, b0, acc[1][0]);
            acc[1][1] = f2fma(ad1, b1, acc[1][1]);
            acc[2][0] = f2fma(ad2, b0, acc[2][0]);
            acc[2][1] = f2fma(ad2, b1, acc[2][1]);
            acc[3][0] = f2fma(ad3, b0, acc[3][0]);
            acc[3][1] = f2fma(ad3, b1, acc[3][1]);
        }
        __syncthreads();
    }

#pragma unroll
    for (int i = 0; i < 4; i++) {
        int o = m0 + 4 * ty + i;
        float bias = g_beff[o];
        float* dst;
        if (o < 128)      dst = g_q + (size_t)(b * 128 + o) * N_;
        else if (o < 256) dst = g_k + (size_t)(b * 128 + (o - 128)) * N_;
        else              dst = g_v + (size_t)(b * 512 + (o - 256)) * N_;
#pragma unroll
        for (int p = 0; p < 2; p++) {
            float lo, hi; f2upk(acc[i][p], lo, hi);
            float2 w; w.x = lo + bias; w.y = hi + bias;
            *reinterpret_cast<float2*>(dst + n0 + 2 * tx + 32 * p) = w;
        }
    }
}

// ---------------- kernel 4: fused flash attention + residual ---------------
// Warp-level layout v2 (smem-traffic-minimizing):
//   warp w owns rows 8w..8w+7 (warp-uniform) — Q reads are pure broadcast.
//   lane L owns S cols {2L,2L+1} and O cols {2L,2L+1,64+2L,64+2L+1} —
//   K and V reads are fully distinct across the warp (no half-warp duplication).
// Smem: Qs[64][68] (16B-aligned rows for float4 Q), Ks[64][68], Vs[64][130].
// P in registers; GEMM2 p[row][s] via __shfl (src lane = s>>1, reg = s&1).
#define QP 68
#define VP 130
#define ATTN_SMEM_FLOATS (2 * 64 * QP + 64 * VP)
#define ATTN_SMEM_BYTES  (ATTN_SMEM_FLOATS * 4)

__global__ __launch_bounds__(256, 3) void attn_kernel(const float* __restrict__ x,
                                                      float* __restrict__ out)
{
    extern __shared__ __align__(16) float sm[];
    float* Qs = sm;                 // Qs[d*QP + r]
    float* Ks = sm + 64 * QP;       // Ks[d*QP + s]
    float* Vs = sm + 2 * 64 * QP;   // Vs[s*VP + c]

    int n0 = blockIdx.x * 64;
    int h  = blockIdx.y;
    int b  = blockIdx.z;
    int tid = threadIdx.x;
    int wid = tid >> 5;             // warp 0..7 -> rows 8*wid..8*wid+7
    int L   = tid & 31;             // lane -> col pair 2L, 2L+1
    int r0  = 8 * wid;

    const float* qbh  = g_q + (size_t)(b * 128 + h * 32) * N_;   // [d][n]
    const float* kbh  = g_k + (size_t)(b * 128 + h * 32) * N_;
    const float* vbh  = g_v + (size_t)(b * 512 + h * 128) * N_;  // [c][n]
    const float* posh = g_pos + (size_t)h * 32 * N_;

    // fill Q' (q rows then pos rows), transposed: Qs[d][r]
    for (int idx = tid; idx < 64 * 64; idx += 256) {
        int r = idx & 63, d = idx >> 6;
        Qs[d * QP + r] = (d < 32) ? qbh[(size_t)d * N_ + n0 + r]
                                  : posh[(size_t)(d - 32) * N_ + n0 + r];
    }

    float m[8], l[8];
    ull O2[8][2];
#pragma unroll
    for (int i = 0; i < 8; i++) {
        m[i] = -1e30f; l[i] = 0.f;
        O2[i][0] = 0ull; O2[i][1] = 0ull;
    }
    __syncthreads();

    for (int s0 = 0; s0 < N_; s0 += 64) {
        // fill K' = [k ; q] (transposed) and V (transposed: Vs[s][c])
        for (int idx = tid; idx < 64 * 64; idx += 256) {
            int s = idx & 63, d = idx >> 6;
            Ks[d * QP + s] = (d < 32) ? kbh[(size_t)d * N_ + s0 + s]
                                      : qbh[(size_t)(d - 32) * N_ + s0 + s];
        }
        for (int idx = tid; idx < 64 * 64; idx += 256) {
            int s = idx & 63, cp = idx >> 6;
            float2 w;
            w.x = vbh[(size_t)(2 * cp) * N_ + s0 + s];
            w.y = vbh[(size_t)(2 * cp + 1) * N_ + s0 + s];
            *reinterpret_cast<float2*>(Vs + s * VP + 2 * cp) = w;
        }
        __syncthreads();

        // GEMM1: S[8 rows x 64 cols] per warp; lane computes 8 rows x 2 cols.
        // Q reads: warp-uniform broadcast.  K reads: 256 B/warp, all distinct.
        ull S2[8];
#pragma unroll
        for (int i = 0; i < 8; i++) S2[i] = 0ull;

#pragma unroll 4
        for (int d = 0; d < 64; d++) {
            float4 qa = *(const float4*)(Qs + d * QP + r0);       // uniform
            float4 qb = *(const float4*)(Qs + d * QP + r0 + 4);   // uniform
            ull k01 = lds64(Ks + d * QP + 2 * L);                 // distinct
            S2[0] = f2fma(f2dup(qa.x), k01, S2[0]);
            S2[1] = f2fma(f2dup(qa.y), k01, S2[1]);
            S2[2] = f2fma(f2dup(qa.z), k01, S2[2]);
            S2[3] = f2fma(f2dup(qa.w), k01, S2[3]);
            S2[4] = f2fma(f2dup(qb.x), k01, S2[4]);
            S2[5] = f2fma(f2dup(qb.y), k01, S2[5]);
            S2[6] = f2fma(f2dup(qb.z), k01, S2[6]);
            S2[7] = f2fma(f2dup(qb.w), k01, S2[7]);
        }

        // online softmax across the full warp (64 cols spread over 32 lanes)
        float P4[8][2];
#pragma unroll
        for (int i = 0; i < 8; i++) {
            float s0v, s1v;
            f2upk(S2[i], s0v, s1v);
            float rm = fmaxf(s0v, s1v);
#pragma unroll
            for (int off = 16; off >= 1; off >>= 1)
                rm = fmaxf(rm, __shfl_xor_sync(0xffffffffu, rm, off));
            float mn = fmaxf(m[i], rm);
            float corr = __expf(m[i] - mn);
            m[i] = mn;
            float p0 = __expf(s0v - mn), p1 = __expf(s1v - mn);
            float rs = p0 + p1;
#pragma unroll
            for (int off = 16; off >= 1; off >>= 1)
                rs += __shfl_xor_sync(0xffffffffu, rs, off);
            l[i] = l[i] * corr + rs;
            ull cd = f2dup(corr);
            O2[i][0] = f2mul(O2[i][0], cd);
            O2[i][1] = f2mul(O2[i][1], cd);
            P4[i][0] = p0; P4[i][1] = p1;
        }
        // GEMM2 consumes P via intra-warp shuffles (no CTA sync needed here)

        // GEMM2: O[8 rows x 128 cols] per warp.  V reads fully distinct
        // (512 B/warp/s).  p[row][s] from lane s>>1, reg s&1.
#pragma unroll 2
        for (int s2 = 0; s2 < 32; s2++) {
            // s = 2*s2 (even -> P4[.][0])
            {
                int s = 2 * s2;
                ull va = lds64(Vs + s * VP + 2 * L);
                ull vb = lds64(Vs + s * VP + 64 + 2 * L);
#pragma unroll
                for (int i = 0; i < 8; i++) {
                    ull pd = f2dup(__shfl_sync(0xffffffffu, P4[i][0], s2));
                    O2[i][0] = f2fma(pd, va, O2[i][0]);
                    O2[i][1] = f2fma(pd, vb, O2[i][1]);
                }
            }
            // s = 2*s2+1 (odd -> P4[.][1])
            {
                int s = 2 * s2 + 1;
                ull va = lds64(Vs + s * VP + 2 * L);
                ull vb = lds64(Vs + s * VP + 64 + 2 * L);
#pragma unroll
                for (int i = 0; i < 8; i++) {
                    ull pd = f2dup(__shfl_sync(0xffffffffu, P4[i][1], s2));
                    O2[i][0] = f2fma(pd, va, O2[i][0]);
                    O2[i][1] = f2fma(pd, vb, O2[i][1]);
                }
            }
        }
        __syncthreads();   // protects Ks/Vs reuse next iteration
    }

    // normalize + transpose through smem for coalesced global writes
    float* Os = sm;   // Os[c*65 + r]: 128*65 = 8320 floats <= Qs+Ks region
#pragma unroll
    for (int i = 0; i < 8; i++) {
        float inv = 1.f / l[i];
        int r = r0 + i;
        float c0, c1, c2, c3;
        f2upk(O2[i][0], c0, c1);
        f2upk(O2[i][1], c2, c3);
        Os[(2 * L)      * 65 + r] = c0 * inv;
        Os[(2 * L + 1)  * 65 + r] = c1 * inv;
        Os[(64 + 2 * L) * 65 + r] = c2 * inv;
        Os[(65 + 2 * L) * 65 + r] = c3 * inv;
    }
    __syncthreads();

    const float* xb = x   + (size_t)(b * 512 + h * 128) * N_;
    float*       ob = out + (size_t)(b * 512 + h * 128) * N_;
    for (int idx = tid; idx < 128 * 64; idx += 256) {
        int r = idx & 63, c = idx >> 6;
        ob[(size_t)c * N_ + n0 + r] = Os[c * 65 + r] + xb[(size_t)c * N_ + n0 + r];
    }
}

// ---------------- launcher -------------------------------------------------
extern "C" void kernel_launch(void* const* d_in, const int* in_sizes, int n_in,
                              void* d_out, int out_size)
{
    const float* x = (const float*)d_in[0];

    fold_kernel<<<(OTOT * CIN + 255) / 256, 256>>>(
        (const float*)d_in[1],  (const float*)d_in[2],
        (const float*)d_in[3],  (const float*)d_in[4],
        (const float*)d_in[5],  (const float*)d_in[6],
        (const float*)d_in[7],  (const float*)d_in[8],
        (const float*)d_in[9],  (const float*)d_in[10],
        (const float*)d_in[11], (const float*)d_in[12],
        (const float*)d_in[13], (const float*)d_in[14],
        (const float*)d_in[15], (const float*)d_in[16],
        (const float*)d_in[17], (const float*)d_in[18]);

    pos_kernel<<<(HEADS_ * DH_ * N_ + 255) / 256, 256>>>(
        (const float*)d_in[19], (const float*)d_in[20]);

    qkv_gemm<<<dim3(N_ / 64, OTOT / 64, B_), 256>>>(x);

    cudaFuncSetAttribute(attn_kernel,
                         cudaFuncAttributeMaxDynamicSharedMemorySize,
                         ATTN_SMEM_BYTES);
    attn_kernel<<<dim3(N_ / 64, HEADS_, B_), 256, ATTN_SMEM_BYTES>>>(x, (float*)d_out);
}